// round 13
// baseline (speedup 1.0000x reference)
#include <cuda_runtime.h>
#include <cuda_bf16.h>
#include <math.h>

typedef unsigned long long ull;

#define HW (512*512)
#define NBH 96   // persistent head blocks (<=148 SMs, 1 block/SM co-residency)

__device__ float g_bufA[3 * 16 * 512 * 512];
__device__ float g_bufB[3 * 16 * 512 * 512];

// ---------------------------------------------------------------------------
// Prepped-weight scratch.
// ---------------------------------------------------------------------------
#define O1 0
#define O2 33792
#define O3 66560
#define O4 82944
#define O5 91136
#define O6 99328
#define O7 103424
#define O8 105472
#define OF 107520
#define WPREP_TOT 108384
__device__ ull g_wprep[WPREP_TOT];

// grid barrier state (monotonic release; graph-replay-safe)
__device__ unsigned int g_arrive = 0;
__device__ unsigned int g_release = 0;

__device__ __forceinline__ void grid_sync() {
    __syncthreads();
    if (threadIdx.x == 0) {
        __threadfence();
        unsigned r = atomicAdd(&g_release, 0u);
        unsigned a = atomicAdd(&g_arrive, 1u);
        if (a == (unsigned)NBH - 1u) {
            atomicExch(&g_arrive, 0u);
            atomicAdd(&g_release, 1u);
        } else {
            while (atomicAdd(&g_release, 0u) == r) { __nanosleep(128); }
        }
        __threadfence();
    }
    __syncthreads();
}

__device__ __forceinline__ int reflect_idx(int u, int S) {
    u = (u < 0) ? -u : u;
    u = (u >= S) ? (2 * S - 2 - u) : u;
    return u;
}

__device__ __forceinline__ ull pack2(float lo, float hi) {
    ull r; asm("mov.b64 %0, {%1, %2};" : "=l"(r) : "f"(lo), "f"(hi)); return r;
}
__device__ __forceinline__ void unpack2(float& lo, float& hi, ull v) {
    asm("mov.b64 {%0, %1}, %2;" : "=f"(lo), "=f"(hi) : "l"(v));
}
__device__ __forceinline__ ull fma2(ull a, ull b, ull c) {
    ull d; asm("fma.rn.f32x2 %0, %1, %2, %3;" : "=l"(d) : "l"(a), "l"(b), "l"(c)); return d;
}
__device__ __forceinline__ ull add2(ull a, ull b) {
    ull d; asm("add.rn.f32x2 %0, %1, %2;" : "=l"(d) : "l"(a), "l"(b)); return d;
}

__device__ __forceinline__ float comb_w(const float* w9, int py, int ry, int px, int rx) {
    const int lo_t[4] = {0, 1, 0, 2};
    const int hi_t[4] = {0, 2, 1, 2};
    int klo = lo_t[py * 2 + ry], khi = hi_t[py * 2 + ry];
    int clo = lo_t[px * 2 + rx], chi = hi_t[px * 2 + rx];
    float s = 0.f;
    for (int ky = klo; ky <= khi; ky++)
        for (int kx = clo; kx <= chi; kx++)
            s += w9[ky * 3 + kx];
    return s;
}

__device__ __forceinline__ ull prep_small2(const float* w, int IN_CH, int e) {
    int op = e / (IN_CH * 16); int rem = e % (IN_CH * 16);
    int ic = rem >> 4; int pp = (rem >> 2) & 3; int tap = rem & 3;
    int py = pp >> 1, px = pp & 1, ry = tap >> 1, rx = tap & 1;
    const float* w9a = w + (2 * op * IN_CH + ic) * 9;
    const float* w9b = w9a + IN_CH * 9;
    return pack2(comb_w(w9a, py, ry, px, rx), comb_w(w9b, py, ry, px, rx));
}

__device__ __forceinline__ ull prep_up2(const float* w, int IN_CH, int CB, int e) {
    int per = 8 * CB * IN_CH;
    int ocb = e / per; int i = e % per;
    int ic = i % IN_CH; int r = i / IN_CH;
    int cb = r % CB; r /= CB;
    int t = r % 2; r /= 2;
    int ry = r % 2; int py = r / 2;
    const float* w9 = w + ((ocb * CB + cb) * IN_CH + ic) * 9;
    return pack2(comb_w(w9, py, ry, 0, t), comb_w(w9, py, ry, 1, t));
}

// ---------------------------------------------------------------------------
// Small-layer phase (device fn): parity-combined 4-tap, ic-reduction split,
// smem staging; chunk loop over work-blocks with stride NBH.
// ---------------------------------------------------------------------------
template<int IN_CH, int OUT_CH, int S_IN, int G, int PREP_OFF>
__device__ void small_phase(const float* __restrict__ in,
                            const float* __restrict__ bias,
                            float* __restrict__ out,
                            float* inp, ull* wsh, ull* parts)
{
    constexpr int S_OUT = 2 * S_IN;
    constexpr int PIX = S_OUT * S_OUT;
    constexpr int NOP = OUT_CH / 2;
    constexpr int NG = NOP / G;
    constexpr int PIXB = 64 / G;
    constexpr int PC = PIX / PIXB;
    constexpr int CPR = (IN_CH + 3) / 4;
    constexpr int WSH_N = G * 16 * IN_CH;
    constexpr int IN_N = IN_CH * S_IN * S_IN;
    constexpr int TOTB = 3 * NG * PC;

    int tid = threadIdx.x;

    for (int u = blockIdx.x; u < TOTB; u += NBH) {
        int b = u;
        int pc = b % PC; b /= PC;
        int g  = b % NG; int n = b / NG;

        const float4* inN4 = reinterpret_cast<const float4*>(in + n * IN_N);
        float4* inp4 = reinterpret_cast<float4*>(inp);
        for (int i = tid; i < IN_N / 4; i += 256) inp4[i] = __ldg(inN4 + i);

        const ulonglong2* wsrc2 = reinterpret_cast<const ulonglong2*>(
            g_wprep + PREP_OFF + (g * G) * IN_CH * 16);
        ulonglong2* wsh2 = reinterpret_cast<ulonglong2*>(wsh);
        for (int i = tid; i < WSH_N / 2; i += 256) wsh2[i] = __ldg(wsrc2 + i);
        __syncthreads();

        int r = tid >> 6;
        int w = tid & 63;
        int gl = w / PIXB;
        int pix = pc * PIXB + (w % PIXB);
        int op = g * G + gl;
        int oc0 = 2 * op;

        int oy = pix / S_OUT, ox = pix % S_OUT;
        int pp = (oy & 1) * 2 + (ox & 1);
        int rA = reflect_idx(oy - 1, S_OUT) >> 1;
        int rB = reflect_idx(oy + 1, S_OUT) >> 1;
        int cA = reflect_idx(ox - 1, S_OUT) >> 1;
        int cB = reflect_idx(ox + 1, S_OUT) >> 1;
        int iA = rA * S_IN, iB = rB * S_IN;

        ull z = pack2(0.f, 0.f);
        ull acc0 = z, acc1 = z, acc2 = z, acc3 = z;

        const ull* wbase = wsh + gl * IN_CH * 16 + pp * 4;
        int ic0 = r * CPR;
        int ic1 = (ic0 + CPR < IN_CH) ? ic0 + CPR : IN_CH;

        #pragma unroll 4
        for (int ic = ic0; ic < ic1; ic++) {
            const float* ib = inp + ic * S_IN * S_IN;
            float v00 = ib[iA + cA];
            float v01 = ib[iA + cB];
            float v10 = ib[iB + cA];
            float v11 = ib[iB + cB];
            const ull* wp = wbase + ic * 16;
            acc0 = fma2(wp[0], pack2(v00, v00), acc0);
            acc1 = fma2(wp[1], pack2(v01, v01), acc1);
            acc2 = fma2(wp[2], pack2(v10, v10), acc2);
            acc3 = fma2(wp[3], pack2(v11, v11), acc3);
        }
        parts[tid] = add2(add2(acc0, acc1), add2(acc2, acc3));
        __syncthreads();

        if (r == 0) {
            ull tot = add2(add2(parts[w], parts[w + 64]),
                           add2(parts[w + 128], parts[w + 192]));
            tot = add2(tot, pack2(__ldg(bias + oc0), __ldg(bias + oc0 + 1)));
            float lo, hi;
            unpack2(lo, hi, tot);
            lo = (lo > 0.f) ? lo : 0.01f * lo;
            hi = (hi > 0.f) ? hi : 0.01f * hi;
            out[(n * OUT_CH + oc0) * PIX + pix] = lo;
            out[(n * OUT_CH + oc0 + 1) * PIX + pix] = hi;
        }
        __syncthreads();   // smem reuse for next chunk
    }
}

// ---------------------------------------------------------------------------
// Persistent fused head: weight prep + L0 + L1..L4, grid-synced phases.
// Dynamic smem layout: inp [0, 32768), wsh [32768, 66560), parts [66560, 68608)
// ---------------------------------------------------------------------------
__global__ void __launch_bounds__(256) head_fused(
    const float* __restrict__ xin,
    const float* __restrict__ w0, const float* __restrict__ b0,
    const float* __restrict__ w1, const float* __restrict__ b1,
    const float* __restrict__ w2, const float* __restrict__ b2,
    const float* __restrict__ w3, const float* __restrict__ b3,
    const float* __restrict__ w4, const float* __restrict__ b4,
    const float* __restrict__ w5, const float* __restrict__ w6,
    const float* __restrict__ w7, const float* __restrict__ w8,
    const float* __restrict__ wfin,
    float* __restrict__ bufA, float* __restrict__ bufB)
{
    extern __shared__ char smem[];
    float* inp = reinterpret_cast<float*>(smem);
    ull* wsh   = reinterpret_cast<ull*>(smem + 32768);
    ull* parts = reinterpret_cast<ull*>(smem + 66560);

    int tid = threadIdx.x;
    int gtid = blockIdx.x * 256 + tid;

    // Phase 0: weight prep + L0
    for (int e = gtid; e < WPREP_TOT; e += NBH * 256) {
        ull v;
        if      (e < O2) v = prep_small2(w1, 66, e - O1);
        else if (e < O3) v = prep_small2(w2, 64, e - O2);
        else if (e < O4) v = prep_small2(w3, 64, e - O3);
        else if (e < O5) v = prep_small2(w4, 32, e - O4);
        else if (e < O6) v = prep_up2(w5, 32, 1, e - O5);
        else if (e < O7) v = prep_up2(w6, 32, 1, e - O6);
        else if (e < O8) v = prep_up2(w7, 16, 2, e - O7);
        else if (e < OF) v = prep_up2(w8, 16, 2, e - O8);
        else             { float wv = wfin[e - OF]; v = pack2(wv, wv); }
        g_wprep[e] = v;
    }
    if (gtid < 3 * 66 * 4) {
        int px = gtid & 3; int t = gtid >> 2;
        int oc = t % 66;  int n = t / 66;
        float v;
        if (oc < 64) {
            v = __ldg(b0 + oc);
            #pragma unroll
            for (int ic = 0; ic < 3; ic++)
                v = fmaf(__ldg(w0 + oc * 3 + ic), __ldg(xin + n * 3 + ic), v);
            v = (v > 0.f) ? v : 0.01f * v;
        } else {
            int yy = px >> 1, xx = px & 1;
            v = (oc == 64) ? 2.f * (float)xx : 2.f * (float)yy;
        }
        bufA[(n * 66 + oc) * 4 + px] = v;
    }
    grid_sync();
    small_phase<66, 64, 2, 4, O1>(bufA, b1, bufB, inp, wsh, parts);   // (3,64,4,4)
    grid_sync();
    small_phase<64, 64, 4, 1, O2>(bufB, b2, bufA, inp, wsh, parts);   // (3,64,8,8)
    grid_sync();
    small_phase<64, 32, 8, 1, O3>(bufA, b3, bufB, inp, wsh, parts);   // (3,32,16,16)
    grid_sync();
    small_phase<32, 32, 16, 1, O4>(bufB, b4, bufA, inp, wsh, parts);  // (3,32,32,32)
}

// ---------------------------------------------------------------------------
// Pipelined row fetch/build for conv_up2.
// ---------------------------------------------------------------------------
struct Row { float4 q; float e0, e5; };

template<int S_IN, bool SHFL>
__device__ __forceinline__ Row fetch_row(const float* __restrict__ row, int m, int lane)
{
    Row r;
    r.q = *reinterpret_cast<const float4*>(row + m);
    if (SHFL) {
        r.e0 = (lane == 0 && m > 0) ? __ldg(row + m - 1) : 0.f;
        r.e5 = (lane == 31 && m + 4 < S_IN) ? __ldg(row + m + 4) : 0.f;
    } else {
        r.e0 = (m > 0) ? __ldg(row + m - 1) : 0.f;
        r.e5 = (m + 4 < S_IN) ? __ldg(row + m + 4) : 0.f;
    }
    return r;
}

template<int S_IN, bool SHFL>
__device__ __forceinline__ void build_pairs(const Row& r, int m, int lane, ull* s)
{
    float d0, d5;
    if (SHFL) {
        d0 = __shfl_up_sync(0xffffffffu, r.q.w, 1);
        d5 = __shfl_down_sync(0xffffffffu, r.q.x, 1);
        if (lane == 0)  d0 = (m > 0) ? r.e0 : r.q.x;
        if (lane == 31) d5 = (m + 4 < S_IN) ? r.e5 : r.q.w;
    } else {
        d0 = (m > 0) ? r.e0 : r.q.x;
        d5 = (m + 4 < S_IN) ? r.e5 : r.q.w;
    }
    s[0] = pack2(d0, r.q.x); s[1] = pack2(r.q.x, r.q.y); s[2] = pack2(r.q.y, r.q.z);
    s[3] = pack2(r.q.z, r.q.w); s[4] = pack2(r.q.w, d5);
}

// ---------------------------------------------------------------------------
// L5..L8: 2-row quad scheme, 2-deep software pipeline on input rows.
// ---------------------------------------------------------------------------
template<int IN_CH, int OUT_CH, int CB, int S_IN, int TPB, int PREP_OFF, bool SHFL>
__global__ void __launch_bounds__(TPB) conv_up2(const float* __restrict__ in,
                                                const float* __restrict__ bias,
                                                float* __restrict__ out)
{
    constexpr int S_OUT = 2 * S_IN;
    constexpr int NXB = S_IN / 4;
    constexpr int NOCB = OUT_CH / CB;
    constexpr int STR = CB * IN_CH;
    constexpr int WN = 8 * STR;

    __shared__ ull wsm[WN];
    __shared__ float bsm[CB];

    int tid = threadIdx.x;
    int n   = blockIdx.y / NOCB;
    int ocb = blockIdx.y % NOCB;

    const ull* wsrc = g_wprep + PREP_OFF + ocb * WN;
    for (int i = tid; i < WN; i += TPB) wsm[i] = wsrc[i];
    if (tid < CB) bsm[tid] = bias[ocb * CB + tid];
    __syncthreads();

    int t = blockIdx.x * TPB + tid;
    int lane = tid & 31;
    int y = t / NXB;
    int g = t % NXB;
    int m = 4 * g;
    int ox0 = 8 * g;

    int r0 = (y > 0) ? y - 1 : 0;
    int r2 = (y < S_IN - 1) ? y + 1 : S_IN - 1;

    ull acc0[CB][4], acc1[CB][4];
    #pragma unroll
    for (int cb = 0; cb < CB; cb++) {
        float bv = bsm[cb];
        ull pb = pack2(bv, bv);
        #pragma unroll
        for (int j = 0; j < 4; j++) { acc0[cb][j] = pb; acc1[cb][j] = pb; }
    }

    const float* inN = in + n * IN_CH * S_IN * S_IN;

    Row cA = fetch_row<S_IN, SHFL>(inN + r0 * S_IN, m, lane);
    Row cB = fetch_row<S_IN, SHFL>(inN + y  * S_IN, m, lane);
    Row cC = fetch_row<S_IN, SHFL>(inN + r2 * S_IN, m, lane);
    const float* b1 = inN + ((IN_CH > 1) ? 1 : 0) * S_IN * S_IN;
    Row p1A = fetch_row<S_IN, SHFL>(b1 + r0 * S_IN, m, lane);
    Row p1B = fetch_row<S_IN, SHFL>(b1 + y  * S_IN, m, lane);
    Row p1C = fetch_row<S_IN, SHFL>(b1 + r2 * S_IN, m, lane);

    #pragma unroll 1
    for (int ic = 0; ic < IN_CH; ic++) {
        int ic2 = (ic + 2 < IN_CH) ? ic + 2 : IN_CH - 1;
        const float* nb = inN + ic2 * S_IN * S_IN;
        Row p2A = fetch_row<S_IN, SHFL>(nb + r0 * S_IN, m, lane);
        Row p2B = fetch_row<S_IN, SHFL>(nb + y  * S_IN, m, lane);
        Row p2C = fetch_row<S_IN, SHFL>(nb + r2 * S_IN, m, lane);

        ull sA[5], sB[5], sC[5];
        build_pairs<S_IN, SHFL>(cA, m, lane, sA);
        build_pairs<S_IN, SHFL>(cB, m, lane, sB);
        build_pairs<S_IN, SHFL>(cC, m, lane, sC);

        #pragma unroll
        for (int cb = 0; cb < CB; cb++) {
            const ull* wp = wsm + cb * IN_CH + ic;
            ull w00A = wp[0 * STR], w00B = wp[1 * STR];
            ull w01A = wp[2 * STR], w01B = wp[3 * STR];
            ull w10A = wp[4 * STR], w10B = wp[5 * STR];
            ull w11A = wp[6 * STR], w11B = wp[7 * STR];
            #pragma unroll
            for (int j = 0; j < 4; j++) {
                acc0[cb][j] = fma2(w00A, sA[j], acc0[cb][j]);
                acc0[cb][j] = fma2(w00B, sA[j + 1], acc0[cb][j]);
                acc0[cb][j] = fma2(w01A, sB[j], acc0[cb][j]);
                acc0[cb][j] = fma2(w01B, sB[j + 1], acc0[cb][j]);
                acc1[cb][j] = fma2(w10A, sB[j], acc1[cb][j]);
                acc1[cb][j] = fma2(w10B, sB[j + 1], acc1[cb][j]);
                acc1[cb][j] = fma2(w11A, sC[j], acc1[cb][j]);
                acc1[cb][j] = fma2(w11B, sC[j + 1], acc1[cb][j]);
            }
        }
        cA = p1A; cB = p1B; cC = p1C;
        p1A = p2A; p1B = p2B; p1C = p2C;
    }

    float* outN = out + ((n * OUT_CH + ocb * CB) * S_OUT) * S_OUT;
    #pragma unroll
    for (int cb = 0; cb < CB; cb++) {
        float* o0 = outN + cb * S_OUT * S_OUT + (2 * y) * S_OUT + ox0;
        float* o1 = o0 + S_OUT;
        #pragma unroll
        for (int rr = 0; rr < 2; rr++) {
            ull* acc = rr ? acc1[cb] : acc0[cb];
            float* op = rr ? o1 : o0;
            float v[8];
            #pragma unroll
            for (int j = 0; j < 4; j++) {
                float lo, hi;
                unpack2(lo, hi, acc[j]);
                v[2 * j] = (lo > 0.f) ? lo : 0.01f * lo;
                v[2 * j + 1] = (hi > 0.f) ? hi : 0.01f * hi;
            }
            float4 q0 = {v[0], v[1], v[2], v[3]};
            float4 q1 = {v[4], v[5], v[6], v[7]};
            *reinterpret_cast<float4*>(op) = q0;
            *reinterpret_cast<float4*>(op + 4) = q1;
        }
    }
}

// ---------------------------------------------------------------------------
// Final layer: reflect-pad 1 + 3x3 conv 16->6 + tanh; 2-deep pipelined rows.
// ---------------------------------------------------------------------------
struct Row8 { float4 qa, qb; float e0, e9; };

__device__ __forceinline__ Row8 fetch_row8(const float* __restrict__ row, int ox0, int lane)
{
    Row8 r;
    r.qa = *reinterpret_cast<const float4*>(row + ox0);
    r.qb = *reinterpret_cast<const float4*>(row + ox0 + 4);
    r.e0 = (lane == 0 && ox0 > 0) ? __ldg(row + ox0 - 1) : 0.f;
    r.e9 = (lane == 31 && ox0 + 8 < 512) ? __ldg(row + ox0 + 8) : 0.f;
    return r;
}

template<int IN_CH, int OUT_CH, int OCB>
__global__ void __launch_bounds__(256) conv_final(const float* __restrict__ in,
                                                  const float* __restrict__ bias,
                                                  float* __restrict__ out)
{
    constexpr int S = 512;
    constexpr int NXB = S / 8;
    constexpr int NOG = OUT_CH / OCB;
    constexpr int WN = OCB * IN_CH * 9;
    constexpr int NK = IN_CH * 3;

    __shared__ ull wsm[WN];
    __shared__ float bsm[OCB];

    int tid = threadIdx.x;
    int n  = blockIdx.y / NOG;
    int og = blockIdx.y % NOG;

    const ull* wsrc = g_wprep + OF + og * WN;
    for (int i = tid; i < WN; i += 256) wsm[i] = wsrc[i];
    if (tid < OCB) bsm[tid] = bias[og * OCB + tid];
    __syncthreads();

    int t = blockIdx.x * 256 + tid;
    int lane = tid & 31;
    int oy  = t / NXB;
    int ox0 = (t % NXB) * 8;

    int iy[3];
    #pragma unroll
    for (int k = 0; k < 3; k++) iy[k] = reflect_idx(oy + k - 1, S);

    ull acc[OCB][4];
    #pragma unroll
    for (int cb = 0; cb < OCB; cb++) {
        float bv = bsm[cb];
        ull pb = pack2(bv, bv);
        #pragma unroll
        for (int j = 0; j < 4; j++) acc[cb][j] = pb;
    }

    const float* inN = in + n * IN_CH * S * S;

    Row8 cur = fetch_row8(inN + iy[0] * S, ox0, lane);
    Row8 nx1 = fetch_row8(inN + iy[1] * S, ox0, lane);

    #pragma unroll 1
    for (int k = 0; k < NK; k++) {
        int k2 = (k + 2 < NK) ? k + 2 : NK - 1;
        int ic2 = k2 / 3, ky2 = k2 % 3;
        Row8 nx2 = fetch_row8(inN + (ic2 * S + iy[ky2]) * S, ox0, lane);

        int ic = k / 3, ky = k % 3;
        float4 qa = cur.qa, qb = cur.qb;
        float d0 = __shfl_up_sync(0xffffffffu, qb.w, 1);
        float d9 = __shfl_down_sync(0xffffffffu, qa.x, 1);
        if (lane == 0)  d0 = (ox0 > 0) ? cur.e0 : qa.y;
        if (lane == 31) d9 = (ox0 + 8 < S) ? cur.e9 : qb.z;
        ull ee[5] = { pack2(d0, qa.x), pack2(qa.y, qa.z), pack2(qa.w, qb.x),
                      pack2(qb.y, qb.z), pack2(qb.w, d9) };
        ull oo[4] = { pack2(qa.x, qa.y), pack2(qa.z, qa.w),
                      pack2(qb.x, qb.y), pack2(qb.z, qb.w) };

        const ull* wR = wsm + ic * 9 + ky * 3;
        #pragma unroll
        for (int cb = 0; cb < OCB; cb++) {
            ull w0 = wR[cb * IN_CH * 9 + 0];
            ull w1 = wR[cb * IN_CH * 9 + 1];
            ull w2 = wR[cb * IN_CH * 9 + 2];
            #pragma unroll
            for (int j = 0; j < 4; j++) {
                acc[cb][j] = fma2(w0, ee[j], acc[cb][j]);
                acc[cb][j] = fma2(w1, oo[j], acc[cb][j]);
                acc[cb][j] = fma2(w2, ee[j + 1], acc[cb][j]);
            }
        }
        cur = nx1;
        nx1 = nx2;
    }

    float* outN = out + ((n * OUT_CH + og * OCB) * S + oy) * S + ox0;
    #pragma unroll
    for (int cb = 0; cb < OCB; cb++) {
        float v[8];
        #pragma unroll
        for (int j = 0; j < 4; j++) {
            float lo, hi;
            unpack2(lo, hi, acc[cb][j]);
            v[2 * j] = tanhf(lo);
            v[2 * j + 1] = tanhf(hi);
        }
        float4 q0 = {v[0], v[1], v[2], v[3]};
        float4 q1 = {v[4], v[5], v[6], v[7]};
        float* op = outN + cb * S * S;
        *reinterpret_cast<float4*>(op) = q0;
        *reinterpret_cast<float4*>(op + 4) = q1;
    }
}

// ---------------------------------------------------------------------------
// Blending kernel
// ---------------------------------------------------------------------------
__global__ void blending_kernel(const float* __restrict__ xin,
                                const float* __restrict__ neighbors,
                                const int*   __restrict__ albedo_index,
                                const float* __restrict__ albedos,
                                const float* __restrict__ flows,
                                float* __restrict__ out)
{
    int tid = blockIdx.x * blockDim.x + threadIdx.x;
    if (tid >= HW) return;
    int px = tid & 511;
    int py = tid >> 9;

    const float* alb = albedos + albedo_index[0] * 3 * HW;

    float x0 = __ldg(xin + 0), x1 = __ldg(xin + 1), x2 = __ldg(xin + 2);

    float f0[6];
    #pragma unroll
    for (int c = 0; c < 6; c++) f0[c] = flows[c * HW + tid];

    float xs = -1.f + 2.f * (float)px / 511.f;
    float ys = -1.f + 2.f * (float)py / 511.f;

    float alb_c[3];
    #pragma unroll
    for (int c = 0; c < 3; c++) alb_c[c] = alb[c * HW + tid];

    float num[3] = {0.f, 0.f, 0.f};
    float den = 0.f;

    #pragma unroll
    for (int n = 0; n < 2; n++) {
        float dl = x0 - __ldg(xin + (n + 1) * 3 + 0);
        float dv = x1 - __ldg(xin + (n + 1) * 3 + 1);
        float dt = x2 - __ldg(xin + (n + 1) * 3 + 2);
        float flag = (fabsf(dl) > 0.f) ? 1.f : 0.f;

        float ofx = dl * f0[0] + dv * f0[2] + dt * f0[4];
        float ofy = dl * f0[1] + dv * f0[3] + dt * f0[5];

        float gx = xs + ofx, gy = ys + ofy;
        float gpx = fminf(fmaxf((gx + 1.f) * 256.f - 0.5f, 0.f), 511.f);
        float gpy = fminf(fmaxf((gy + 1.f) * 256.f - 0.5f, 0.f), 511.f);
        float x0f = floorf(gpx), y0f = floorf(gpy);
        float wx = gpx - x0f, wy = gpy - y0f;
        int x0i = (int)x0f; x0i = max(0, min(x0i, 511));
        int x1i = min(x0i + 1, 511);
        int y0i = (int)y0f; y0i = max(0, min(y0i, 511));
        int y1i = min(y0i + 1, 511);

        float w00 = (1.f - wx) * (1.f - wy);
        float w01 = wx * (1.f - wy);
        float w10 = (1.f - wx) * wy;
        float w11 = wx * wy;
        int i00 = y0i * 512 + x0i, i01 = y0i * 512 + x1i;
        int i10 = y1i * 512 + x0i, i11 = y1i * 512 + x1i;

        const float* nb = neighbors + n * 3 * HW;
        const float* fn = flows + (n + 1) * 6 * HW;

        float wimg[3];
        #pragma unroll
        for (int c = 0; c < 3; c++) {
            const float* nbc = nb + c * HW;
            const float* ac  = alb + c * HW;
            float s00 = flag * __fdividef(nbc[i00], ac[i00]) + (1.f - flag) * nbc[i00];
            float s01 = flag * __fdividef(nbc[i01], ac[i01]) + (1.f - flag) * nbc[i01];
            float s10 = flag * __fdividef(nbc[i10], ac[i10]) + (1.f - flag) * nbc[i10];
            float s11 = flag * __fdividef(nbc[i11], ac[i11]) + (1.f - flag) * nbc[i11];
            float wsv = w00 * s00 + w01 * s01 + w10 * s10 + w11 * s11;
            wimg[c] = flag * wsv * alb_c[c] + (1.f - flag) * wsv;
        }

        float wfv[6];
        #pragma unroll
        for (int c = 0; c < 6; c++) {
            const float* fc = fn + c * HW;
            wfv[c] = w00 * fc[i00] + w01 * fc[i01] + w10 * fc[i10] + w11 * fc[i11];
        }
        float obx = dl * wfv[0] + dv * wfv[2] + dt * wfv[4];
        float oby = dl * wfv[1] + dv * wfv[3] + dt * wfv[5];
        float dist = fabsf(ofx - obx) + fabsf(ofy - oby);
        float wgt = __expf(-51.2f * dist);

        #pragma unroll
        for (int c = 0; c < 3; c++) num[c] += wimg[c] * wgt;
        den += wgt;
    }

    float inv = __fdividef(1.f, den + 1e-5f);
    #pragma unroll
    for (int c = 0; c < 3; c++) out[c * HW + tid] = num[c] * inv;
}

// ---------------------------------------------------------------------------
// Launch. Inputs: 0:x 1:neighbors 2:albedo_index, 3+2i:w{i} 4+2i:b{i},
//                 21:wf 22:bf 23:albedos
// ---------------------------------------------------------------------------
extern "C" void kernel_launch(void* const* d_in, const int* in_sizes, int n_in,
                              void* d_out, int out_size)
{
    const float* x          = (const float*)d_in[0];
    const float* neighbors  = (const float*)d_in[1];
    const int*   albedo_idx = (const int*)d_in[2];
    const float* w[9]; const float* b[9];
    for (int i = 0; i < 9; i++) {
        w[i] = (const float*)d_in[3 + 2 * i];
        b[i] = (const float*)d_in[4 + 2 * i];
    }
    const float* wf      = (const float*)d_in[21];
    const float* bf      = (const float*)d_in[22];
    const float* albedos = (const float*)d_in[23];
    float* out = (float*)d_out;

    float *pA = nullptr, *pB = nullptr;
    cudaGetSymbolAddress((void**)&pA, g_bufA);
    cudaGetSymbolAddress((void**)&pB, g_bufB);

    static bool attr_set = false;
    if (!attr_set) {
        cudaFuncSetAttribute(head_fused, cudaFuncAttributeMaxDynamicSharedMemorySize, 69632);
        attr_set = true;
    }

    // Fused: weight prep + L0..L4 (output in bufA, (3,32,32,32))
    head_fused<<<NBH, 256, 68608>>>(x, w[0], b[0], w[1], b[1], w[2], b[2],
                                    w[3], b[3], w[4], b[4],
                                    w[5], w[6], w[7], w[8], wf, pA, pB);

    conv_up2<32, 32, 1,  32, 128, O5, false><<<dim3( 2, 96), 128>>>(pA, b[5], pB); // (3,32,64,64)
    conv_up2<32, 16, 1,  64, 128, O6, false><<<dim3( 8, 48), 128>>>(pB, b[6], pA); // (3,16,128,128)
    conv_up2<16, 16, 2, 128, 256, O7, true ><<<dim3(16, 24), 256>>>(pA, b[7], pB); // (3,16,256,256)
    conv_up2<16, 16, 2, 256, 256, O8, true ><<<dim3(64, 24), 256>>>(pB, b[8], pA); // (3,16,512,512)
    conv_final<16, 6, 2><<<dim3(128, 9), 256>>>(pA, bf, pB);                       // flows

    blending_kernel<<<(HW + 255) / 256, 256>>>(x, neighbors, albedo_idx, albedos, pB, out);
}

// round 14
// speedup vs baseline: 1.1106x; 1.1106x over previous
#include <cuda_runtime.h>
#include <cuda_bf16.h>
#include <math.h>

typedef unsigned long long ull;

#define HW (512*512)

__device__ float g_bufA[3 * 16 * 512 * 512];
__device__ float g_bufB[3 * 16 * 512 * 512];

// ---------------------------------------------------------------------------
// Prepped-weight scratch.
// ---------------------------------------------------------------------------
#define O1 0
#define O2 33792
#define O3 66560
#define O4 82944
#define O5 91136
#define O6 99328
#define O7 103424
#define O8 105472
#define OF 107520
#define WPREP_TOT 108384
__device__ ull g_wprep[WPREP_TOT];

__device__ __forceinline__ int reflect_idx(int u, int S) {
    u = (u < 0) ? -u : u;
    u = (u >= S) ? (2 * S - 2 - u) : u;
    return u;
}

__device__ __forceinline__ ull pack2(float lo, float hi) {
    ull r; asm("mov.b64 %0, {%1, %2};" : "=l"(r) : "f"(lo), "f"(hi)); return r;
}
__device__ __forceinline__ void unpack2(float& lo, float& hi, ull v) {
    asm("mov.b64 {%0, %1}, %2;" : "=f"(lo), "=f"(hi) : "l"(v));
}
__device__ __forceinline__ ull fma2(ull a, ull b, ull c) {
    ull d; asm("fma.rn.f32x2 %0, %1, %2, %3;" : "=l"(d) : "l"(a), "l"(b), "l"(c)); return d;
}
__device__ __forceinline__ ull add2(ull a, ull b) {
    ull d; asm("add.rn.f32x2 %0, %1, %2;" : "=l"(d) : "l"(a), "l"(b)); return d;
}

__device__ __forceinline__ float comb_w(const float* w9, int py, int ry, int px, int rx) {
    const int lo_t[4] = {0, 1, 0, 2};
    const int hi_t[4] = {0, 2, 1, 2};
    int klo = lo_t[py * 2 + ry], khi = hi_t[py * 2 + ry];
    int clo = lo_t[px * 2 + rx], chi = hi_t[px * 2 + rx];
    float s = 0.f;
    for (int ky = klo; ky <= khi; ky++)
        for (int kx = clo; kx <= chi; kx++)
            s += w9[ky * 3 + kx];
    return s;
}

__device__ __forceinline__ ull prep_small2(const float* w, int IN_CH, int e) {
    int op = e / (IN_CH * 16); int rem = e % (IN_CH * 16);
    int ic = rem >> 4; int pp = (rem >> 2) & 3; int tap = rem & 3;
    int py = pp >> 1, px = pp & 1, ry = tap >> 1, rx = tap & 1;
    const float* w9a = w + (2 * op * IN_CH + ic) * 9;
    const float* w9b = w9a + IN_CH * 9;
    return pack2(comb_w(w9a, py, ry, px, rx), comb_w(w9b, py, ry, px, rx));
}

__device__ __forceinline__ ull prep_up2(const float* w, int IN_CH, int CB, int e) {
    int per = 8 * CB * IN_CH;
    int ocb = e / per; int i = e % per;
    int ic = i % IN_CH; int r = i / IN_CH;
    int cb = r % CB; r /= CB;
    int t = r % 2; r /= 2;
    int ry = r % 2; int py = r / 2;
    const float* w9 = w + ((ocb * CB + cb) * IN_CH + ic) * 9;
    return pack2(comb_w(w9, py, ry, 0, t), comb_w(w9, py, ry, 1, t));
}

// ---------------------------------------------------------------------------
// Fused weight prep + layer0
// ---------------------------------------------------------------------------
__global__ void prep_and_l0(const float* __restrict__ w1, const float* __restrict__ w2,
                            const float* __restrict__ w3, const float* __restrict__ w4,
                            const float* __restrict__ w5, const float* __restrict__ w6,
                            const float* __restrict__ w7, const float* __restrict__ w8,
                            const float* __restrict__ wf,
                            const float* __restrict__ xin,
                            const float* __restrict__ w0, const float* __restrict__ b0,
                            float* __restrict__ outL0)
{
    int e = blockIdx.x * 256 + threadIdx.x;
    if (e < WPREP_TOT) {
        ull v;
        if      (e < O2) v = prep_small2(w1, 66, e - O1);
        else if (e < O3) v = prep_small2(w2, 64, e - O2);
        else if (e < O4) v = prep_small2(w3, 64, e - O3);
        else if (e < O5) v = prep_small2(w4, 32, e - O4);
        else if (e < O6) v = prep_up2(w5, 32, 1, e - O5);
        else if (e < O7) v = prep_up2(w6, 32, 1, e - O6);
        else if (e < O8) v = prep_up2(w7, 16, 2, e - O7);
        else if (e < OF) v = prep_up2(w8, 16, 2, e - O8);
        else             { float wv = wf[e - OF]; v = pack2(wv, wv); }
        g_wprep[e] = v;
    } else {
        int tid = e - WPREP_TOT;
        if (tid < 3 * 66 * 4) {
            int px = tid & 3; int t = tid >> 2;
            int oc = t % 66;  int n = t / 66;
            float v;
            if (oc < 64) {
                v = __ldg(b0 + oc);
                #pragma unroll
                for (int ic = 0; ic < 3; ic++)
                    v = fmaf(__ldg(w0 + oc * 3 + ic), __ldg(xin + n * 3 + ic), v);
                v = (v > 0.f) ? v : 0.01f * v;
            } else {
                int yy = px >> 1, xx = px & 1;
                v = (oc == 64) ? 2.f * (float)xx : 2.f * (float)yy;
            }
            outL0[(n * 66 + oc) * 4 + px] = v;
        }
    }
}

// ---------------------------------------------------------------------------
// L1..L4: parity-combined 4-tap with ic-reduction split; float4 staging.
// ---------------------------------------------------------------------------
template<int IN_CH, int OUT_CH, int S_IN, int G, int PREP_OFF>
__global__ void __launch_bounds__(256) conv_small_r(const float* __restrict__ in,
                                                    const float* __restrict__ bias,
                                                    float* __restrict__ out)
{
    constexpr int S_OUT = 2 * S_IN;
    constexpr int PIX = S_OUT * S_OUT;
    constexpr int NOP = OUT_CH / 2;
    constexpr int NG = NOP / G;
    constexpr int PIXB = 64 / G;
    constexpr int PC = PIX / PIXB;
    constexpr int CPR = (IN_CH + 3) / 4;
    constexpr int WSH_N = G * 16 * IN_CH;
    constexpr int IN_N = IN_CH * S_IN * S_IN;
    static_assert(IN_N % 4 == 0, "float4 staging");
    static_assert(WSH_N % 2 == 0, "u2 staging");

    __shared__ float inp[IN_N];
    __shared__ ull wsh[WSH_N];
    __shared__ ull parts[256];

    int tid = threadIdx.x;
    int b = blockIdx.x;
    int pc = b % PC; b /= PC;
    int g  = b % NG; int n = b / NG;

    const float4* inN4 = reinterpret_cast<const float4*>(in + n * IN_N);
    float4* inp4 = reinterpret_cast<float4*>(inp);
    #pragma unroll
    for (int i = tid; i < IN_N / 4; i += 256) inp4[i] = __ldg(inN4 + i);

    const ulonglong2* wsrc2 = reinterpret_cast<const ulonglong2*>(
        g_wprep + PREP_OFF + (g * G) * IN_CH * 16);
    ulonglong2* wsh2 = reinterpret_cast<ulonglong2*>(wsh);
    #pragma unroll
    for (int i = tid; i < WSH_N / 2; i += 256) wsh2[i] = __ldg(wsrc2 + i);
    __syncthreads();

    int r = tid >> 6;
    int w = tid & 63;
    int gl = w / PIXB;
    int pix = pc * PIXB + (w % PIXB);
    int op = g * G + gl;
    int oc0 = 2 * op;

    int oy = pix / S_OUT, ox = pix % S_OUT;
    int pp = (oy & 1) * 2 + (ox & 1);
    int rA = reflect_idx(oy - 1, S_OUT) >> 1;
    int rB = reflect_idx(oy + 1, S_OUT) >> 1;
    int cA = reflect_idx(ox - 1, S_OUT) >> 1;
    int cB = reflect_idx(ox + 1, S_OUT) >> 1;
    int iA = rA * S_IN, iB = rB * S_IN;

    ull z = pack2(0.f, 0.f);
    ull acc0 = z, acc1 = z, acc2 = z, acc3 = z;

    const ull* wbase = wsh + gl * IN_CH * 16 + pp * 4;
    int ic0 = r * CPR;
    int ic1 = (ic0 + CPR < IN_CH) ? ic0 + CPR : IN_CH;

    #pragma unroll 4
    for (int ic = ic0; ic < ic1; ic++) {
        const float* ib = inp + ic * S_IN * S_IN;
        float v00 = ib[iA + cA];
        float v01 = ib[iA + cB];
        float v10 = ib[iB + cA];
        float v11 = ib[iB + cB];
        const ull* wp = wbase + ic * 16;
        acc0 = fma2(wp[0], pack2(v00, v00), acc0);
        acc1 = fma2(wp[1], pack2(v01, v01), acc1);
        acc2 = fma2(wp[2], pack2(v10, v10), acc2);
        acc3 = fma2(wp[3], pack2(v11, v11), acc3);
    }
    parts[tid] = add2(add2(acc0, acc1), add2(acc2, acc3));
    __syncthreads();

    if (r == 0) {
        ull tot = add2(add2(parts[w], parts[w + 64]),
                       add2(parts[w + 128], parts[w + 192]));
        tot = add2(tot, pack2(bias[oc0], bias[oc0 + 1]));
        float lo, hi;
        unpack2(lo, hi, tot);
        lo = (lo > 0.f) ? lo : 0.01f * lo;
        hi = (hi > 0.f) ? hi : 0.01f * hi;
        out[(n * OUT_CH + oc0) * PIX + pix] = lo;
        out[(n * OUT_CH + oc0 + 1) * PIX + pix] = hi;
    }
}

// ---------------------------------------------------------------------------
// Pipelined row fetch/build for conv_up2.
// ---------------------------------------------------------------------------
struct Row { float4 q; float e0, e5; };

template<int S_IN, bool SHFL>
__device__ __forceinline__ Row fetch_row(const float* __restrict__ row, int m, int lane)
{
    Row r;
    r.q = *reinterpret_cast<const float4*>(row + m);
    if (SHFL) {
        r.e0 = (lane == 0 && m > 0) ? __ldg(row + m - 1) : 0.f;
        r.e5 = (lane == 31 && m + 4 < S_IN) ? __ldg(row + m + 4) : 0.f;
    } else {
        r.e0 = (m > 0) ? __ldg(row + m - 1) : 0.f;
        r.e5 = (m + 4 < S_IN) ? __ldg(row + m + 4) : 0.f;
    }
    return r;
}

template<int S_IN, bool SHFL>
__device__ __forceinline__ void build_pairs(const Row& r, int m, int lane, ull* s)
{
    float d0, d5;
    if (SHFL) {
        d0 = __shfl_up_sync(0xffffffffu, r.q.w, 1);
        d5 = __shfl_down_sync(0xffffffffu, r.q.x, 1);
        if (lane == 0)  d0 = (m > 0) ? r.e0 : r.q.x;
        if (lane == 31) d5 = (m + 4 < S_IN) ? r.e5 : r.q.w;
    } else {
        d0 = (m > 0) ? r.e0 : r.q.x;
        d5 = (m + 4 < S_IN) ? r.e5 : r.q.w;
    }
    s[0] = pack2(d0, r.q.x); s[1] = pack2(r.q.x, r.q.y); s[2] = pack2(r.q.y, r.q.z);
    s[3] = pack2(r.q.z, r.q.w); s[4] = pack2(r.q.w, d5);
}

// ---------------------------------------------------------------------------
// L5..L8: 2-row quad scheme, 2-deep software pipeline, ic-loop unrolled x2
// so the pipeline register copies are renamed away by ptxas.
// ---------------------------------------------------------------------------
template<int IN_CH, int OUT_CH, int CB, int S_IN, int TPB, int PREP_OFF, bool SHFL>
__global__ void __launch_bounds__(TPB) conv_up2(const float* __restrict__ in,
                                                const float* __restrict__ bias,
                                                float* __restrict__ out)
{
    constexpr int S_OUT = 2 * S_IN;
    constexpr int NXB = S_IN / 4;
    constexpr int NOCB = OUT_CH / CB;
    constexpr int STR = CB * IN_CH;
    constexpr int WN = 8 * STR;

    __shared__ ull wsm[WN];
    __shared__ float bsm[CB];

    int tid = threadIdx.x;
    int n   = blockIdx.y / NOCB;
    int ocb = blockIdx.y % NOCB;

    const ull* wsrc = g_wprep + PREP_OFF + ocb * WN;
    for (int i = tid; i < WN; i += TPB) wsm[i] = wsrc[i];
    if (tid < CB) bsm[tid] = bias[ocb * CB + tid];
    __syncthreads();

    int t = blockIdx.x * TPB + tid;
    int lane = tid & 31;
    int y = t / NXB;
    int g = t % NXB;
    int m = 4 * g;
    int ox0 = 8 * g;

    int r0 = (y > 0) ? y - 1 : 0;
    int r2 = (y < S_IN - 1) ? y + 1 : S_IN - 1;

    ull acc0[CB][4], acc1[CB][4];
    #pragma unroll
    for (int cb = 0; cb < CB; cb++) {
        float bv = bsm[cb];
        ull pb = pack2(bv, bv);
        #pragma unroll
        for (int j = 0; j < 4; j++) { acc0[cb][j] = pb; acc1[cb][j] = pb; }
    }

    const float* inN = in + n * IN_CH * S_IN * S_IN;

    Row cA = fetch_row<S_IN, SHFL>(inN + r0 * S_IN, m, lane);
    Row cB = fetch_row<S_IN, SHFL>(inN + y  * S_IN, m, lane);
    Row cC = fetch_row<S_IN, SHFL>(inN + r2 * S_IN, m, lane);
    const float* b1 = inN + ((IN_CH > 1) ? 1 : 0) * S_IN * S_IN;
    Row p1A = fetch_row<S_IN, SHFL>(b1 + r0 * S_IN, m, lane);
    Row p1B = fetch_row<S_IN, SHFL>(b1 + y  * S_IN, m, lane);
    Row p1C = fetch_row<S_IN, SHFL>(b1 + r2 * S_IN, m, lane);

    #pragma unroll 2
    for (int ic = 0; ic < IN_CH; ic++) {
        int ic2 = (ic + 2 < IN_CH) ? ic + 2 : IN_CH - 1;
        const float* nb = inN + ic2 * S_IN * S_IN;
        Row p2A = fetch_row<S_IN, SHFL>(nb + r0 * S_IN, m, lane);
        Row p2B = fetch_row<S_IN, SHFL>(nb + y  * S_IN, m, lane);
        Row p2C = fetch_row<S_IN, SHFL>(nb + r2 * S_IN, m, lane);

        ull sA[5], sB[5], sC[5];
        build_pairs<S_IN, SHFL>(cA, m, lane, sA);
        build_pairs<S_IN, SHFL>(cB, m, lane, sB);
        build_pairs<S_IN, SHFL>(cC, m, lane, sC);

        #pragma unroll
        for (int cb = 0; cb < CB; cb++) {
            const ull* wp = wsm + cb * IN_CH + ic;
            ull w00A = wp[0 * STR], w00B = wp[1 * STR];
            ull w01A = wp[2 * STR], w01B = wp[3 * STR];
            ull w10A = wp[4 * STR], w10B = wp[5 * STR];
            ull w11A = wp[6 * STR], w11B = wp[7 * STR];
            #pragma unroll
            for (int j = 0; j < 4; j++) {
                acc0[cb][j] = fma2(w00A, sA[j], acc0[cb][j]);
                acc0[cb][j] = fma2(w00B, sA[j + 1], acc0[cb][j]);
                acc0[cb][j] = fma2(w01A, sB[j], acc0[cb][j]);
                acc0[cb][j] = fma2(w01B, sB[j + 1], acc0[cb][j]);
                acc1[cb][j] = fma2(w10A, sB[j], acc1[cb][j]);
                acc1[cb][j] = fma2(w10B, sB[j + 1], acc1[cb][j]);
                acc1[cb][j] = fma2(w11A, sC[j], acc1[cb][j]);
                acc1[cb][j] = fma2(w11B, sC[j + 1], acc1[cb][j]);
            }
        }
        cA = p1A; cB = p1B; cC = p1C;
        p1A = p2A; p1B = p2B; p1C = p2C;
    }

    float* outN = out + ((n * OUT_CH + ocb * CB) * S_OUT) * S_OUT;
    #pragma unroll
    for (int cb = 0; cb < CB; cb++) {
        float* o0 = outN + cb * S_OUT * S_OUT + (2 * y) * S_OUT + ox0;
        float* o1 = o0 + S_OUT;
        #pragma unroll
        for (int rr = 0; rr < 2; rr++) {
            ull* acc = rr ? acc1[cb] : acc0[cb];
            float* op = rr ? o1 : o0;
            float v[8];
            #pragma unroll
            for (int j = 0; j < 4; j++) {
                float lo, hi;
                unpack2(lo, hi, acc[j]);
                v[2 * j] = (lo > 0.f) ? lo : 0.01f * lo;
                v[2 * j + 1] = (hi > 0.f) ? hi : 0.01f * hi;
            }
            float4 q0 = {v[0], v[1], v[2], v[3]};
            float4 q1 = {v[4], v[5], v[6], v[7]};
            *reinterpret_cast<float4*>(op) = q0;
            *reinterpret_cast<float4*>(op + 4) = q1;
        }
    }
}

// ---------------------------------------------------------------------------
// Final layer: reflect-pad 1 + 3x3 conv 16->6 + tanh; 2-deep pipeline,
// k-loop unrolled x3 (one ic per unrolled body) for register renaming.
// ---------------------------------------------------------------------------
struct Row8 { float4 qa, qb; float e0, e9; };

__device__ __forceinline__ Row8 fetch_row8(const float* __restrict__ row, int ox0, int lane)
{
    Row8 r;
    r.qa = *reinterpret_cast<const float4*>(row + ox0);
    r.qb = *reinterpret_cast<const float4*>(row + ox0 + 4);
    r.e0 = (lane == 0 && ox0 > 0) ? __ldg(row + ox0 - 1) : 0.f;
    r.e9 = (lane == 31 && ox0 + 8 < 512) ? __ldg(row + ox0 + 8) : 0.f;
    return r;
}

template<int IN_CH, int OUT_CH, int OCB>
__global__ void __launch_bounds__(256) conv_final(const float* __restrict__ in,
                                                  const float* __restrict__ bias,
                                                  float* __restrict__ out)
{
    constexpr int S = 512;
    constexpr int NXB = S / 8;
    constexpr int NOG = OUT_CH / OCB;
    constexpr int WN = OCB * IN_CH * 9;
    constexpr int NK = IN_CH * 3;

    __shared__ ull wsm[WN];
    __shared__ float bsm[OCB];

    int tid = threadIdx.x;
    int n  = blockIdx.y / NOG;
    int og = blockIdx.y % NOG;

    const ull* wsrc = g_wprep + OF + og * WN;
    for (int i = tid; i < WN; i += 256) wsm[i] = wsrc[i];
    if (tid < OCB) bsm[tid] = bias[og * OCB + tid];
    __syncthreads();

    int t = blockIdx.x * 256 + tid;
    int lane = tid & 31;
    int oy  = t / NXB;
    int ox0 = (t % NXB) * 8;

    int iy[3];
    #pragma unroll
    for (int k = 0; k < 3; k++) iy[k] = reflect_idx(oy + k - 1, S);

    ull acc[OCB][4];
    #pragma unroll
    for (int cb = 0; cb < OCB; cb++) {
        float bv = bsm[cb];
        ull pb = pack2(bv, bv);
        #pragma unroll
        for (int j = 0; j < 4; j++) acc[cb][j] = pb;
    }

    const float* inN = in + n * IN_CH * S * S;

    Row8 cur = fetch_row8(inN + iy[0] * S, ox0, lane);
    Row8 nx1 = fetch_row8(inN + iy[1] * S, ox0, lane);

    #pragma unroll 3
    for (int k = 0; k < NK; k++) {
        int k2 = (k + 2 < NK) ? k + 2 : NK - 1;
        int ic2 = k2 / 3, ky2 = k2 % 3;
        Row8 nx2 = fetch_row8(inN + (ic2 * S + iy[ky2]) * S, ox0, lane);

        int ic = k / 3, ky = k % 3;
        float4 qa = cur.qa, qb = cur.qb;
        float d0 = __shfl_up_sync(0xffffffffu, qb.w, 1);
        float d9 = __shfl_down_sync(0xffffffffu, qa.x, 1);
        if (lane == 0)  d0 = (ox0 > 0) ? cur.e0 : qa.y;
        if (lane == 31) d9 = (ox0 + 8 < S) ? cur.e9 : qb.z;
        ull ee[5] = { pack2(d0, qa.x), pack2(qa.y, qa.z), pack2(qa.w, qb.x),
                      pack2(qb.y, qb.z), pack2(qb.w, d9) };
        ull oo[4] = { pack2(qa.x, qa.y), pack2(qa.z, qa.w),
                      pack2(qb.x, qb.y), pack2(qb.z, qb.w) };

        const ull* wR = wsm + ic * 9 + ky * 3;
        #pragma unroll
        for (int cb = 0; cb < OCB; cb++) {
            ull w0 = wR[cb * IN_CH * 9 + 0];
            ull w1 = wR[cb * IN_CH * 9 + 1];
            ull w2 = wR[cb * IN_CH * 9 + 2];
            #pragma unroll
            for (int j = 0; j < 4; j++) {
                acc[cb][j] = fma2(w0, ee[j], acc[cb][j]);
                acc[cb][j] = fma2(w1, oo[j], acc[cb][j]);
                acc[cb][j] = fma2(w2, ee[j + 1], acc[cb][j]);
            }
        }
        cur = nx1;
        nx1 = nx2;
    }

    float* outN = out + ((n * OUT_CH + og * OCB) * S + oy) * S + ox0;
    #pragma unroll
    for (int cb = 0; cb < OCB; cb++) {
        float v[8];
        #pragma unroll
        for (int j = 0; j < 4; j++) {
            float lo, hi;
            unpack2(lo, hi, acc[cb][j]);
            v[2 * j] = tanhf(lo);
            v[2 * j + 1] = tanhf(hi);
        }
        float4 q0 = {v[0], v[1], v[2], v[3]};
        float4 q1 = {v[4], v[5], v[6], v[7]};
        float* op = outN + cb * S * S;
        *reinterpret_cast<float4*>(op) = q0;
        *reinterpret_cast<float4*>(op + 4) = q1;
    }
}

// ---------------------------------------------------------------------------
// Blending kernel
// ---------------------------------------------------------------------------
__global__ void blending_kernel(const float* __restrict__ xin,
                                const float* __restrict__ neighbors,
                                const int*   __restrict__ albedo_index,
                                const float* __restrict__ albedos,
                                const float* __restrict__ flows,
                                float* __restrict__ out)
{
    int tid = blockIdx.x * blockDim.x + threadIdx.x;
    if (tid >= HW) return;
    int px = tid & 511;
    int py = tid >> 9;

    const float* alb = albedos + albedo_index[0] * 3 * HW;

    float x0 = __ldg(xin + 0), x1 = __ldg(xin + 1), x2 = __ldg(xin + 2);

    float f0[6];
    #pragma unroll
    for (int c = 0; c < 6; c++) f0[c] = flows[c * HW + tid];

    float xs = -1.f + 2.f * (float)px / 511.f;
    float ys = -1.f + 2.f * (float)py / 511.f;

    float alb_c[3];
    #pragma unroll
    for (int c = 0; c < 3; c++) alb_c[c] = alb[c * HW + tid];

    float num[3] = {0.f, 0.f, 0.f};
    float den = 0.f;

    #pragma unroll
    for (int n = 0; n < 2; n++) {
        float dl = x0 - __ldg(xin + (n + 1) * 3 + 0);
        float dv = x1 - __ldg(xin + (n + 1) * 3 + 1);
        float dt = x2 - __ldg(xin + (n + 1) * 3 + 2);
        float flag = (fabsf(dl) > 0.f) ? 1.f : 0.f;

        float ofx = dl * f0[0] + dv * f0[2] + dt * f0[4];
        float ofy = dl * f0[1] + dv * f0[3] + dt * f0[5];

        float gx = xs + ofx, gy = ys + ofy;
        float gpx = fminf(fmaxf((gx + 1.f) * 256.f - 0.5f, 0.f), 511.f);
        float gpy = fminf(fmaxf((gy + 1.f) * 256.f - 0.5f, 0.f), 511.f);
        float x0f = floorf(gpx), y0f = floorf(gpy);
        float wx = gpx - x0f, wy = gpy - y0f;
        int x0i = (int)x0f; x0i = max(0, min(x0i, 511));
        int x1i = min(x0i + 1, 511);
        int y0i = (int)y0f; y0i = max(0, min(y0i, 511));
        int y1i = min(y0i + 1, 511);

        float w00 = (1.f - wx) * (1.f - wy);
        float w01 = wx * (1.f - wy);
        float w10 = (1.f - wx) * wy;
        float w11 = wx * wy;
        int i00 = y0i * 512 + x0i, i01 = y0i * 512 + x1i;
        int i10 = y1i * 512 + x0i, i11 = y1i * 512 + x1i;

        const float* nb = neighbors + n * 3 * HW;
        const float* fn = flows + (n + 1) * 6 * HW;

        float wimg[3];
        #pragma unroll
        for (int c = 0; c < 3; c++) {
            const float* nbc = nb + c * HW;
            const float* ac  = alb + c * HW;
            float s00 = flag * __fdividef(nbc[i00], ac[i00]) + (1.f - flag) * nbc[i00];
            float s01 = flag * __fdividef(nbc[i01], ac[i01]) + (1.f - flag) * nbc[i01];
            float s10 = flag * __fdividef(nbc[i10], ac[i10]) + (1.f - flag) * nbc[i10];
            float s11 = flag * __fdividef(nbc[i11], ac[i11]) + (1.f - flag) * nbc[i11];
            float wsv = w00 * s00 + w01 * s01 + w10 * s10 + w11 * s11;
            wimg[c] = flag * wsv * alb_c[c] + (1.f - flag) * wsv;
        }

        float wfv[6];
        #pragma unroll
        for (int c = 0; c < 6; c++) {
            const float* fc = fn + c * HW;
            wfv[c] = w00 * fc[i00] + w01 * fc[i01] + w10 * fc[i10] + w11 * fc[i11];
        }
        float obx = dl * wfv[0] + dv * wfv[2] + dt * wfv[4];
        float oby = dl * wfv[1] + dv * wfv[3] + dt * wfv[5];
        float dist = fabsf(ofx - obx) + fabsf(ofy - oby);
        float wgt = __expf(-51.2f * dist);

        #pragma unroll
        for (int c = 0; c < 3; c++) num[c] += wimg[c] * wgt;
        den += wgt;
    }

    float inv = __fdividef(1.f, den + 1e-5f);
    #pragma unroll
    for (int c = 0; c < 3; c++) out[c * HW + tid] = num[c] * inv;
}

// ---------------------------------------------------------------------------
// Launch. Inputs: 0:x 1:neighbors 2:albedo_index, 3+2i:w{i} 4+2i:b{i},
//                 21:wf 22:bf 23:albedos
// ---------------------------------------------------------------------------
extern "C" void kernel_launch(void* const* d_in, const int* in_sizes, int n_in,
                              void* d_out, int out_size)
{
    const float* x          = (const float*)d_in[0];
    const float* neighbors  = (const float*)d_in[1];
    const int*   albedo_idx = (const int*)d_in[2];
    const float* w[9]; const float* b[9];
    for (int i = 0; i < 9; i++) {
        w[i] = (const float*)d_in[3 + 2 * i];
        b[i] = (const float*)d_in[4 + 2 * i];
    }
    const float* wf      = (const float*)d_in[21];
    const float* bf      = (const float*)d_in[22];
    const float* albedos = (const float*)d_in[23];
    float* out = (float*)d_out;

    float *pA = nullptr, *pB = nullptr;
    cudaGetSymbolAddress((void**)&pA, g_bufA);
    cudaGetSymbolAddress((void**)&pB, g_bufB);

    prep_and_l0<<<(WPREP_TOT + 3 * 66 * 4 + 255) / 256, 256>>>(
        w[1], w[2], w[3], w[4], w[5], w[6], w[7], w[8], wf,
        x, w[0], b[0], pA);                                            // A (3,66,2,2)

    conv_small_r<66, 64, 2, 4, O1><<< 24, 256>>>(pA, b[1], pB);        // B (3,64,4,4)
    conv_small_r<64, 64, 4, 1, O2><<< 96, 256>>>(pB, b[2], pA);        // A (3,64,8,8)
    conv_small_r<64, 32, 8, 1, O3><<<192, 256>>>(pA, b[3], pB);        // B (3,32,16,16)
    conv_small_r<32, 32, 16, 1, O4><<<768, 256>>>(pB, b[4], pA);       // A (3,32,32,32)

    conv_up2<32, 32, 1,  32, 128, O5, false><<<dim3( 2, 96), 128>>>(pA, b[5], pB); // (3,32,64,64)
    conv_up2<32, 16, 1,  64, 128, O6, false><<<dim3( 8, 48), 128>>>(pB, b[6], pA); // (3,16,128,128)
    conv_up2<16, 16, 2, 128, 256, O7, true ><<<dim3(16, 24), 256>>>(pA, b[7], pB); // (3,16,256,256)
    conv_up2<16, 16, 2, 256, 256, O8, true ><<<dim3(64, 24), 256>>>(pB, b[8], pA); // (3,16,512,512)
    conv_final<16, 6, 2><<<dim3(128, 9), 256>>>(pA, bf, pB);                       // flows

    blending_kernel<<<(HW + 255) / 256, 256>>>(x, neighbors, albedo_idx, albedos, pB, out);
}